// round 6
// baseline (speedup 1.0000x reference)
#include <cuda_runtime.h>
#include <math.h>

#define T_STEPS 250
#define NN      256
#define IN_DIM  1024
#define HH      1024
#define OUT_DIM 35
#define BR      4
#define INB     256
#define TC      25                 // timesteps per chunk
#define NCHUNK  (T_STEPS / TC)     // 10
#define MC      (TC * NN)          // 6400 rows per chunk

// Persistent state (device globals: no allocation allowed)
__device__ float g_state[NN * BR * HH];     // 4 MB
__device__ float g_v1[NN * HH];             // 1 MB
__device__ float g_alpha[BR * HH];
__device__ float g_v2[NN * OUT_DIM];
__device__ float g_acc[NN * OUT_DIM];
__device__ float g_Y[(size_t)MC * BR * HH]; // 104.9 MB chunk buffer of branch_in

__global__ void init_kernel(const float* __restrict__ taus) {
    int idx = blockIdx.x * blockDim.x + threadIdx.x;   // 1048576 threads
    g_state[idx] = 0.f;
    if (idx < NN * HH) g_v1[idx] = 0.f;
    if (idx < BR * HH) g_alpha[idx] = 1.f / (1.f + expf(-taus[idx]));
    if (idx < NN * OUT_DIM) { g_v2[idx] = 0.f; g_acc[idx] = 0.f; }
}

// ---------------------------------------------------------------------------
// Batched branch GEMM: Y[r, br, h] = sum_k Xc[r, br*256+k]*Wb[br,k,h] + bb[br,h]
// Block tile 128(M) x 128(H), BK=16, 256 threads, 8x8 per thread,
// f32x2 packed on M-pairs. 2 CTAs/SM for latency hiding.
// ---------------------------------------------------------------------------
__global__ __launch_bounds__(256, 2) void gemm_kernel(
    const float* __restrict__ Xc,   // [MC, IN_DIM] chunk base
    const float* __restrict__ Wb,   // [BR, INB, HH]
    const float* __restrict__ bb)   // [BR, HH]
{
    __shared__ float As[2][16][128];   // [buf][k][m]  (m contiguous)
    __shared__ float Bs[2][16][128];   // [buf][k][h]

    const int tid  = threadIdx.x;
    const int h0v  = blockIdx.x * 128;
    const int m0   = blockIdx.y * 128;
    const int br   = blockIdx.z;

    // compute mapping: 16 m-groups x 16 h-groups
    const int tx = tid & 15;               // h group
    const int ty = tid >> 4;               // m group
    const int mB = ty * 8;                 // m offset within block tile
    const int hB = tx * 8;                 // h offset within block tile

    // loaders
    // A: 128 rows x 16 k; thread: row=tid>>1, k=(tid&1)*8 -> 2 LDG.128
    const int ar = tid >> 1, ak = (tid & 1) * 8;
    const float* aptr = Xc + (size_t)(m0 + ar) * IN_DIM + br * INB + ak;
    // B: 16 k x 128 h; thread: k=tid>>4, h=(tid&15)*8 -> 2 LDG.128
    const int bk = tid >> 4, bh = (tid & 15) * 8;
    const float* bptr = Wb + ((size_t)br * INB + bk) * HH + h0v + bh;

    unsigned long long acc[4][8];          // [m-pair][h]
#pragma unroll
    for (int i = 0; i < 4; ++i)
#pragma unroll
        for (int j = 0; j < 8; ++j) acc[i][j] = 0ULL;

    // prologue: k-tile 0 -> buffer 0
    {
        float4 a0 = *(const float4*)(aptr);
        float4 a1 = *(const float4*)(aptr + 4);
        float4 b0 = *(const float4*)(bptr);
        float4 b1 = *(const float4*)(bptr + 4);
        As[0][ak + 0][ar] = a0.x; As[0][ak + 1][ar] = a0.y;
        As[0][ak + 2][ar] = a0.z; As[0][ak + 3][ar] = a0.w;
        As[0][ak + 4][ar] = a1.x; As[0][ak + 5][ar] = a1.y;
        As[0][ak + 6][ar] = a1.z; As[0][ak + 7][ar] = a1.w;
        *(float4*)&Bs[0][bk][bh]     = b0;
        *(float4*)&Bs[0][bk][bh + 4] = b1;
    }
    __syncthreads();

    int buf = 0;
#pragma unroll 1
    for (int k0 = 0; k0 < INB; k0 += 16) {
        const bool more = (k0 + 16) < INB;
        float4 na0, na1, nb0, nb1;
        if (more) {
            na0 = *(const float4*)(aptr + k0 + 16);
            na1 = *(const float4*)(aptr + k0 + 20);
            nb0 = *(const float4*)(bptr + (size_t)(k0 + 16) * HH);
            nb1 = *(const float4*)(bptr + (size_t)(k0 + 16) * HH + 4);
        }
#pragma unroll
        for (int k = 0; k < 16; ++k) {
            // A: 8 m as 4 packed f32x2 (2x LDS.128, no dup)
            ulonglong2 aq0 = *(const ulonglong2*)&As[buf][k][mB];
            ulonglong2 aq1 = *(const ulonglong2*)&As[buf][k][mB + 4];
            unsigned long long a2p[4] = {aq0.x, aq0.y, aq1.x, aq1.y};
            // B: 8 h scalars (2x LDS.128), duplicated into both lanes
            float4 bf0 = *(const float4*)&Bs[buf][k][hB];
            float4 bf1 = *(const float4*)&Bs[buf][k][hB + 4];
            float bv[8] = {bf0.x, bf0.y, bf0.z, bf0.w,
                           bf1.x, bf1.y, bf1.z, bf1.w};
            unsigned long long bd[8];
#pragma unroll
            for (int j = 0; j < 8; ++j)
                asm("mov.b64 %0, {%1, %1};" : "=l"(bd[j]) : "f"(bv[j]));
#pragma unroll
            for (int i = 0; i < 4; ++i)
#pragma unroll
                for (int j = 0; j < 8; ++j)
                    asm("fma.rn.f32x2 %0, %1, %2, %0;"
                        : "+l"(acc[i][j]) : "l"(a2p[i]), "l"(bd[j]));
        }
        if (more) {
            const int nb = buf ^ 1;
            As[nb][ak + 0][ar] = na0.x; As[nb][ak + 1][ar] = na0.y;
            As[nb][ak + 2][ar] = na0.z; As[nb][ak + 3][ar] = na0.w;
            As[nb][ak + 4][ar] = na1.x; As[nb][ak + 5][ar] = na1.y;
            As[nb][ak + 6][ar] = na1.z; As[nb][ak + 7][ar] = na1.w;
            *(float4*)&Bs[nb][bk][bh]     = nb0;
            *(float4*)&Bs[nb][bk][bh + 4] = nb1;
            __syncthreads();
            buf = nb;
        }
    }

    // epilogue: unpack, add bias, store 8 rows x 8 h
    float4 bias0 = *(const float4*)(bb + br * HH + h0v + hB);
    float4 bias1 = *(const float4*)(bb + br * HH + h0v + hB + 4);
    const float bvv[8] = {bias0.x, bias0.y, bias0.z, bias0.w,
                          bias1.x, bias1.y, bias1.z, bias1.w};
#pragma unroll
    for (int i = 0; i < 4; ++i) {
        float lo[8], hi[8];
#pragma unroll
        for (int j = 0; j < 8; ++j)
            asm("mov.b64 {%0, %1}, %2;" : "=f"(lo[j]), "=f"(hi[j]) : "l"(acc[i][j]));
        size_t r0 = (size_t)(m0 + mB + 2 * i);
        float* yp0 = &g_Y[(r0 * BR + br) * HH + h0v + hB];
        float* yp1 = yp0 + (size_t)BR * HH;
        float4 w;
        w.x = lo[0] + bvv[0]; w.y = lo[1] + bvv[1];
        w.z = lo[2] + bvv[2]; w.w = lo[3] + bvv[3];
        *(float4*)yp0 = w;
        w.x = lo[4] + bvv[4]; w.y = lo[5] + bvv[5];
        w.z = lo[6] + bvv[6]; w.w = lo[7] + bvv[7];
        *(float4*)(yp0 + 4) = w;
        w.x = hi[0] + bvv[0]; w.y = hi[1] + bvv[1];
        w.z = hi[2] + bvv[2]; w.w = hi[3] + bvv[3];
        *(float4*)yp1 = w;
        w.x = hi[4] + bvv[4]; w.y = hi[5] + bvv[5];
        w.z = hi[6] + bvv[6]; w.w = hi[7] + bvv[7];
        *(float4*)(yp1 + 4) = w;
    }
}

// ---------------------------------------------------------------------------
// Fused recurrence over one chunk (unchanged)
// ---------------------------------------------------------------------------
#define W2_STRIDE 36
#define SM_W2   (HH * W2_STRIDE)
#define SM_RED  (2 * 256 * W2_STRIDE)
#define SM_REDP (2 * 4 * W2_STRIDE)
#define SMEM_RECUR_BYTES ((SM_W2 + SM_RED + SM_REDP) * 4)

__global__ __launch_bounds__(512, 1) void recur_kernel(
    const float* __restrict__ W2,
    const float* __restrict__ b2,
    const float* __restrict__ tau1p,
    const float* __restrict__ tau2p)
{
    extern __shared__ float sm[];
    float* W2s  = sm;
    float* red  = sm + SM_W2;
    float* redp = red + SM_RED;

    const int tid = threadIdx.x;
    const int n_l = tid >> 8;
    const int hq  = tid & 255;
    const int n   = blockIdx.x * 2 + n_l;
    const int h0  = hq * 4;

    for (int i = tid; i < SM_W2; i += 512) {
        int h = i / W2_STRIDE, o = i - h * W2_STRIDE;
        W2s[i] = (o < OUT_DIM) ? W2[h * OUT_DIM + o] : 0.f;
    }

    float4 st[BR], al[BR];
#pragma unroll
    for (int b = 0; b < BR; ++b) {
        st[b] = *(float4*)&g_state[((size_t)n * BR + b) * HH + h0];
        al[b] = *(const float4*)&g_alpha[b * HH + h0];
    }
    float4 v1 = *(float4*)&g_v1[(size_t)n * HH + h0];
    const float tau1v = *tau1p, tau2v = *tau2p;

    const bool own = (tid < 72);
    const int o_o = tid % 36, n_o = tid / 36;
    float v2 = 0.f, accv = 0.f, b2v = 0.f;
    int vidx = 0;
    if (own && o_o < OUT_DIM) {
        vidx = (blockIdx.x * 2 + n_o) * OUT_DIM + o_o;
        v2 = g_v2[vidx]; accv = g_acc[vidx]; b2v = b2[o_o];
    }
    __syncthreads();

#pragma unroll 1
    for (int t = 0; t < TC; ++t) {
        float4 cb = {0.f, 0.f, 0.f, 0.f};
#pragma unroll
        for (int b = 0; b < BR; ++b) {
            float4 y = *(const float4*)&g_Y[(((size_t)t * NN + n) * BR + b) * HH + h0];
            st[b].x = al[b].x * st[b].x + (1.f - al[b].x) * y.x;
            st[b].y = al[b].y * st[b].y + (1.f - al[b].y) * y.y;
            st[b].z = al[b].z * st[b].z + (1.f - al[b].z) * y.z;
            st[b].w = al[b].w * st[b].w + (1.f - al[b].w) * y.w;
            cb.x += st[b].x; cb.y += st[b].y; cb.z += st[b].z; cb.w += st[b].w;
        }
        v1.x = v1.x + (cb.x - v1.x) / tau1v;
        v1.y = v1.y + (cb.y - v1.y) / tau1v;
        v1.z = v1.z + (cb.z - v1.z) / tau1v;
        v1.w = v1.w + (cb.w - v1.w) / tau1v;
        float s0 = (v1.x >= 1.f) ? 1.f : 0.f;
        float s1 = (v1.y >= 1.f) ? 1.f : 0.f;
        float s2 = (v1.z >= 1.f) ? 1.f : 0.f;
        float s3 = (v1.w >= 1.f) ? 1.f : 0.f;
        v1.x *= (1.f - s0); v1.y *= (1.f - s1);
        v1.z *= (1.f - s2); v1.w *= (1.f - s3);

        float4 a4[9];
#pragma unroll
        for (int q = 0; q < 9; ++q) a4[q] = make_float4(0.f, 0.f, 0.f, 0.f);
        if (s0 != 0.f) {
            const float4* w = (const float4*)&W2s[(h0 + 0) * W2_STRIDE];
#pragma unroll
            for (int q = 0; q < 9; ++q) { float4 v = w[q];
                a4[q].x += v.x; a4[q].y += v.y; a4[q].z += v.z; a4[q].w += v.w; }
        }
        if (s1 != 0.f) {
            const float4* w = (const float4*)&W2s[(h0 + 1) * W2_STRIDE];
#pragma unroll
            for (int q = 0; q < 9; ++q) { float4 v = w[q];
                a4[q].x += v.x; a4[q].y += v.y; a4[q].z += v.z; a4[q].w += v.w; }
        }
        if (s2 != 0.f) {
            const float4* w = (const float4*)&W2s[(h0 + 2) * W2_STRIDE];
#pragma unroll
            for (int q = 0; q < 9; ++q) { float4 v = w[q];
                a4[q].x += v.x; a4[q].y += v.y; a4[q].z += v.z; a4[q].w += v.w; }
        }
        if (s3 != 0.f) {
            const float4* w = (const float4*)&W2s[(h0 + 3) * W2_STRIDE];
#pragma unroll
            for (int q = 0; q < 9; ++q) { float4 v = w[q];
                a4[q].x += v.x; a4[q].y += v.y; a4[q].z += v.z; a4[q].w += v.w; }
        }
        float* rp = &red[((size_t)n_l * 256 + hq) * W2_STRIDE];
#pragma unroll
        for (int q = 0; q < 9; ++q) *(float4*)(rp + q * 4) = a4[q];
        __syncthreads();

        if (tid < 288) {
            int nl = tid / 144, r = tid % 144;
            int o = r % 36, seg = r / 36;
            const float* c = &red[((size_t)nl * 256 + seg * 64) * W2_STRIDE + o];
            float s = 0.f;
#pragma unroll 8
            for (int j = 0; j < 64; ++j) s += c[(size_t)j * W2_STRIDE];
            redp[(nl * 4 + seg) * W2_STRIDE + o] = s;
        }
        __syncthreads();

        if (own && o_o < OUT_DIM) {
            float h2 = redp[(n_o * 4 + 0) * W2_STRIDE + o_o]
                     + redp[(n_o * 4 + 1) * W2_STRIDE + o_o]
                     + redp[(n_o * 4 + 2) * W2_STRIDE + o_o]
                     + redp[(n_o * 4 + 3) * W2_STRIDE + o_o] + b2v;
            v2 = v2 + (h2 - v2) / tau2v;
            float s = (v2 >= 1.f) ? 1.f : 0.f;
            v2 *= (1.f - s);
            accv += s;
        }
        __syncthreads();
    }

#pragma unroll
    for (int b = 0; b < BR; ++b)
        *(float4*)&g_state[((size_t)n * BR + b) * HH + h0] = st[b];
    *(float4*)&g_v1[(size_t)n * HH + h0] = v1;
    if (own && o_o < OUT_DIM) { g_v2[vidx] = v2; g_acc[vidx] = accv; }
}

// ---------------------------------------------------------------------------
// Final log_softmax
// ---------------------------------------------------------------------------
__global__ void final_kernel(float* __restrict__ out) {
    const int n = threadIdx.x;
    float f[OUT_DIM];
    float m = -1e30f;
#pragma unroll
    for (int o = 0; o < OUT_DIM; ++o) {
        f[o] = g_acc[n * OUT_DIM + o];
        m = fmaxf(m, f[o]);
    }
    float s = 0.f;
#pragma unroll
    for (int o = 0; o < OUT_DIM; ++o) s += expf(f[o] - m);
    float l = logf(s);
#pragma unroll
    for (int o = 0; o < OUT_DIM; ++o) out[n * OUT_DIM + o] = f[o] - m - l;
}

extern "C" void kernel_launch(void* const* d_in, const int* in_sizes, int n_in,
                              void* d_out, int out_size) {
    const float* x    = (const float*)d_in[0];
    const float* Wb   = (const float*)d_in[1];
    const float* bb   = (const float*)d_in[2];
    const float* taus = (const float*)d_in[3];
    const float* W2   = (const float*)d_in[4];
    const float* b2   = (const float*)d_in[5];
    const float* tau1 = (const float*)d_in[6];
    const float* tau2 = (const float*)d_in[7];
    float* out = (float*)d_out;

    static bool attr_set = false;
    if (!attr_set) {
        cudaFuncSetAttribute(recur_kernel,
                             cudaFuncAttributeMaxDynamicSharedMemorySize,
                             SMEM_RECUR_BYTES);
        attr_set = true;
    }

    init_kernel<<<4096, 256>>>(taus);

    dim3 ggrid(HH / 128, MC / 128, BR);   // (8, 50, 4) = 1600 blocks
    for (int c = 0; c < NCHUNK; ++c) {
        const float* Xc = x + (size_t)c * MC * IN_DIM;
        gemm_kernel<<<ggrid, 256>>>(Xc, Wb, bb);
        recur_kernel<<<128, 512, SMEM_RECUR_BYTES>>>(W2, b2, tau1, tau2);
    }
    final_kernel<<<1, 256>>>(out);
}

// round 12
// speedup vs baseline: 1.1441x; 1.1441x over previous
#include <cuda_runtime.h>
#include <cstdint>
#include <math.h>

#define T_STEPS 250
#define NN      256
#define IN_DIM  1024
#define HH      1024
#define OUT_DIM 35
#define BR      4
#define INB     256
#define TC      25
#define NCHUNK  (T_STEPS / TC)     // 10
#define MC      (TC * NN)          // 6400 rows per chunk

// Persistent state (device globals: no allocation allowed)
__device__ float g_state[NN * BR * HH];
__device__ float g_v1[NN * HH];
__device__ float g_alpha[BR * HH];
__device__ float g_v2[NN * OUT_DIM];
__device__ float g_acc[NN * OUT_DIM];
__device__ float g_Y[2][(size_t)MC * BR * HH];   // double-buffered chunk output

__global__ void init_kernel(const float* __restrict__ taus) {
    int idx = blockIdx.x * blockDim.x + threadIdx.x;
    g_state[idx] = 0.f;
    if (idx < NN * HH) g_v1[idx] = 0.f;
    if (idx < BR * HH) g_alpha[idx] = 1.f / (1.f + expf(-taus[idx]));
    if (idx < NN * OUT_DIM) { g_v2[idx] = 0.f; g_acc[idx] = 0.f; }
}

// ---------------------------------------------------------------------------
// Batched branch GEMM (R5 best): tile 256(M) x 128(H), BK=16, 256 threads,
// 16x8 per thread, f32x2 packed on M-pairs.
// ---------------------------------------------------------------------------
__global__ __launch_bounds__(256, 1) void gemm_kernel(
    const float* __restrict__ Xc,   // [MC, IN_DIM] chunk base
    const float* __restrict__ Wb,   // [BR, INB, HH]
    const float* __restrict__ bb,   // [BR, HH]
    int ybuf)
{
    __shared__ float As[2][16][256];
    __shared__ float Bs[2][16][128];

    const int tid  = threadIdx.x;
    const int h0v  = blockIdx.x * 128;
    const int m0   = blockIdx.y * 256;
    const int br   = blockIdx.z;

    const int tx = tid & 15;
    const int ty = tid >> 4;
    const int mB = ty * 16;
    const int hB = tx * 8;

    const float* aptr = Xc + (size_t)(m0 + tid) * IN_DIM + br * INB;
    const int bk = tid >> 4, bh = (tid & 15) * 8;
    const float* bptr = Wb + ((size_t)br * INB + bk) * HH + h0v + bh;

    float* Yb = g_Y[ybuf];

    unsigned long long acc[8][8];
#pragma unroll
    for (int i = 0; i < 8; ++i)
#pragma unroll
        for (int j = 0; j < 8; ++j) acc[i][j] = 0ULL;

    {
        float4 a0 = *(const float4*)(aptr + 0);
        float4 a1 = *(const float4*)(aptr + 4);
        float4 a2 = *(const float4*)(aptr + 8);
        float4 a3 = *(const float4*)(aptr + 12);
        float4 b0 = *(const float4*)(bptr);
        float4 b1 = *(const float4*)(bptr + 4);
        As[0][ 0][tid] = a0.x; As[0][ 1][tid] = a0.y;
        As[0][ 2][tid] = a0.z; As[0][ 3][tid] = a0.w;
        As[0][ 4][tid] = a1.x; As[0][ 5][tid] = a1.y;
        As[0][ 6][tid] = a1.z; As[0][ 7][tid] = a1.w;
        As[0][ 8][tid] = a2.x; As[0][ 9][tid] = a2.y;
        As[0][10][tid] = a2.z; As[0][11][tid] = a2.w;
        As[0][12][tid] = a3.x; As[0][13][tid] = a3.y;
        As[0][14][tid] = a3.z; As[0][15][tid] = a3.w;
        *(float4*)&Bs[0][bk][bh]     = b0;
        *(float4*)&Bs[0][bk][bh + 4] = b1;
    }
    __syncthreads();

    int buf = 0;
#pragma unroll 1
    for (int k0 = 0; k0 < INB; k0 += 16) {
        const bool more = (k0 + 16) < INB;
        float4 na0, na1, na2, na3, nb0, nb1;
        if (more) {
            na0 = *(const float4*)(aptr + k0 + 16);
            na1 = *(const float4*)(aptr + k0 + 20);
            na2 = *(const float4*)(aptr + k0 + 24);
            na3 = *(const float4*)(aptr + k0 + 28);
            nb0 = *(const float4*)(bptr + (size_t)(k0 + 16) * HH);
            nb1 = *(const float4*)(bptr + (size_t)(k0 + 16) * HH + 4);
        }
#pragma unroll
        for (int k = 0; k < 16; ++k) {
            ulonglong2 aq0 = *(const ulonglong2*)&As[buf][k][mB];
            ulonglong2 aq1 = *(const ulonglong2*)&As[buf][k][mB + 4];
            ulonglong2 aq2 = *(const ulonglong2*)&As[buf][k][mB + 8];
            ulonglong2 aq3 = *(const ulonglong2*)&As[buf][k][mB + 12];
            unsigned long long a2p[8] = {aq0.x, aq0.y, aq1.x, aq1.y,
                                         aq2.x, aq2.y, aq3.x, aq3.y};
            float4 bf0 = *(const float4*)&Bs[buf][k][hB];
            float4 bf1 = *(const float4*)&Bs[buf][k][hB + 4];
            float bv[8] = {bf0.x, bf0.y, bf0.z, bf0.w,
                           bf1.x, bf1.y, bf1.z, bf1.w};
            unsigned long long bd[8];
#pragma unroll
            for (int j = 0; j < 8; ++j)
                asm("mov.b64 %0, {%1, %1};" : "=l"(bd[j]) : "f"(bv[j]));
#pragma unroll
            for (int i = 0; i < 8; ++i)
#pragma unroll
                for (int j = 0; j < 8; ++j)
                    asm("fma.rn.f32x2 %0, %1, %2, %0;"
                        : "+l"(acc[i][j]) : "l"(a2p[i]), "l"(bd[j]));
        }
        if (more) {
            const int nb = buf ^ 1;
            As[nb][ 0][tid] = na0.x; As[nb][ 1][tid] = na0.y;
            As[nb][ 2][tid] = na0.z; As[nb][ 3][tid] = na0.w;
            As[nb][ 4][tid] = na1.x; As[nb][ 5][tid] = na1.y;
            As[nb][ 6][tid] = na1.z; As[nb][ 7][tid] = na1.w;
            As[nb][ 8][tid] = na2.x; As[nb][ 9][tid] = na2.y;
            As[nb][10][tid] = na2.z; As[nb][11][tid] = na2.w;
            As[nb][12][tid] = na3.x; As[nb][13][tid] = na3.y;
            As[nb][14][tid] = na3.z; As[nb][15][tid] = na3.w;
            *(float4*)&Bs[nb][bk][bh]     = nb0;
            *(float4*)&Bs[nb][bk][bh + 4] = nb1;
            __syncthreads();
            buf = nb;
        }
    }

    float4 bias0 = *(const float4*)(bb + br * HH + h0v + hB);
    float4 bias1 = *(const float4*)(bb + br * HH + h0v + hB + 4);
    const float bvv[8] = {bias0.x, bias0.y, bias0.z, bias0.w,
                          bias1.x, bias1.y, bias1.z, bias1.w};
#pragma unroll
    for (int i = 0; i < 8; ++i) {
        float lo[8], hi[8];
#pragma unroll
        for (int j = 0; j < 8; ++j)
            asm("mov.b64 {%0, %1}, %2;" : "=f"(lo[j]), "=f"(hi[j]) : "l"(acc[i][j]));
        size_t r0 = (size_t)(m0 + mB + 2 * i);
        float* yp0 = &Yb[(r0 * BR + br) * HH + h0v + hB];
        float* yp1 = yp0 + (size_t)BR * HH;
        float4 w;
        w.x = lo[0] + bvv[0]; w.y = lo[1] + bvv[1];
        w.z = lo[2] + bvv[2]; w.w = lo[3] + bvv[3];
        *(float4*)yp0 = w;
        w.x = lo[4] + bvv[4]; w.y = lo[5] + bvv[5];
        w.z = lo[6] + bvv[6]; w.w = lo[7] + bvv[7];
        *(float4*)(yp0 + 4) = w;
        w.x = hi[0] + bvv[0]; w.y = hi[1] + bvv[1];
        w.z = hi[2] + bvv[2]; w.w = hi[3] + bvv[3];
        *(float4*)yp1 = w;
        w.x = hi[4] + bvv[4]; w.y = hi[5] + bvv[5];
        w.z = hi[6] + bvv[6]; w.w = hi[7] + bvv[7];
        *(float4*)(yp1 + 4) = w;
    }
}

// ---------------------------------------------------------------------------
// Fused recurrence over one chunk (runs on side stream, overlapped)
// ---------------------------------------------------------------------------
#define W2_STRIDE 36
#define SM_W2   (HH * W2_STRIDE)
#define SM_RED  (2 * 256 * W2_STRIDE)
#define SM_REDP (2 * 4 * W2_STRIDE)
#define SMEM_RECUR_BYTES ((SM_W2 + SM_RED + SM_REDP) * 4)

__global__ __launch_bounds__(512, 1) void recur_kernel(
    const float* __restrict__ W2,
    const float* __restrict__ b2,
    const float* __restrict__ tau1p,
    const float* __restrict__ tau2p,
    int ybuf)
{
    extern __shared__ float sm[];
    float* W2s  = sm;
    float* red  = sm + SM_W2;
    float* redp = red + SM_RED;

    const int tid = threadIdx.x;
    const int n_l = tid >> 8;
    const int hq  = tid & 255;
    const int n   = blockIdx.x * 2 + n_l;
    const int h0  = hq * 4;
    const float* Yb = g_Y[ybuf];

    for (int i = tid; i < SM_W2; i += 512) {
        int h = i / W2_STRIDE, o = i - h * W2_STRIDE;
        W2s[i] = (o < OUT_DIM) ? W2[h * OUT_DIM + o] : 0.f;
    }

    float4 st[BR], al[BR];
#pragma unroll
    for (int b = 0; b < BR; ++b) {
        st[b] = *(float4*)&g_state[((size_t)n * BR + b) * HH + h0];
        al[b] = *(const float4*)&g_alpha[b * HH + h0];
    }
    float4 v1 = *(float4*)&g_v1[(size_t)n * HH + h0];
    const float tau1v = *tau1p, tau2v = *tau2p;

    const bool own = (tid < 72);
    const int o_o = tid % 36, n_o = tid / 36;
    float v2 = 0.f, accv = 0.f, b2v = 0.f;
    int vidx = 0;
    if (own && o_o < OUT_DIM) {
        vidx = (blockIdx.x * 2 + n_o) * OUT_DIM + o_o;
        v2 = g_v2[vidx]; accv = g_acc[vidx]; b2v = b2[o_o];
    }
    __syncthreads();

#pragma unroll 1
    for (int t = 0; t < TC; ++t) {
        float4 cb = {0.f, 0.f, 0.f, 0.f};
#pragma unroll
        for (int b = 0; b < BR; ++b) {
            float4 y = *(const float4*)&Yb[(((size_t)t * NN + n) * BR + b) * HH + h0];
            st[b].x = al[b].x * st[b].x + (1.f - al[b].x) * y.x;
            st[b].y = al[b].y * st[b].y + (1.f - al[b].y) * y.y;
            st[b].z = al[b].z * st[b].z + (1.f - al[b].z) * y.z;
            st[b].w = al[b].w * st[b].w + (1.f - al[b].w) * y.w;
            cb.x += st[b].x; cb.y += st[b].y; cb.z += st[b].z; cb.w += st[b].w;
        }
        v1.x = v1.x + (cb.x - v1.x) / tau1v;
        v1.y = v1.y + (cb.y - v1.y) / tau1v;
        v1.z = v1.z + (cb.z - v1.z) / tau1v;
        v1.w = v1.w + (cb.w - v1.w) / tau1v;
        float s0 = (v1.x >= 1.f) ? 1.f : 0.f;
        float s1 = (v1.y >= 1.f) ? 1.f : 0.f;
        float s2 = (v1.z >= 1.f) ? 1.f : 0.f;
        float s3 = (v1.w >= 1.f) ? 1.f : 0.f;
        v1.x *= (1.f - s0); v1.y *= (1.f - s1);
        v1.z *= (1.f - s2); v1.w *= (1.f - s3);

        float4 a4[9];
#pragma unroll
        for (int q = 0; q < 9; ++q) a4[q] = make_float4(0.f, 0.f, 0.f, 0.f);
        if (s0 != 0.f) {
            const float4* w = (const float4*)&W2s[(h0 + 0) * W2_STRIDE];
#pragma unroll
            for (int q = 0; q < 9; ++q) { float4 v = w[q];
                a4[q].x += v.x; a4[q].y += v.y; a4[q].z += v.z; a4[q].w += v.w; }
        }
        if (s1 != 0.f) {
            const float4* w = (const float4*)&W2s[(h0 + 1) * W2_STRIDE];
#pragma unroll
            for (int q = 0; q < 9; ++q) { float4 v = w[q];
                a4[q].x += v.x; a4[q].y += v.y; a4[q].z += v.z; a4[q].w += v.w; }
        }
        if (s2 != 0.f) {
            const float4* w = (const float4*)&W2s[(h0 + 2) * W2_STRIDE];
#pragma unroll
            for (int q = 0; q < 9; ++q) { float4 v = w[q];
                a4[q].x += v.x; a4[q].y += v.y; a4[q].z += v.z; a4[q].w += v.w; }
        }
        if (s3 != 0.f) {
            const float4* w = (const float4*)&W2s[(h0 + 3) * W2_STRIDE];
#pragma unroll
            for (int q = 0; q < 9; ++q) { float4 v = w[q];
                a4[q].x += v.x; a4[q].y += v.y; a4[q].z += v.z; a4[q].w += v.w; }
        }
        float* rp = &red[((size_t)n_l * 256 + hq) * W2_STRIDE];
#pragma unroll
        for (int q = 0; q < 9; ++q) *(float4*)(rp + q * 4) = a4[q];
        __syncthreads();

        if (tid < 288) {
            int nl = tid / 144, r = tid % 144;
            int o = r % 36, seg = r / 36;
            const float* c = &red[((size_t)nl * 256 + seg * 64) * W2_STRIDE + o];
            float s = 0.f;
#pragma unroll 8
            for (int j = 0; j < 64; ++j) s += c[(size_t)j * W2_STRIDE];
            redp[(nl * 4 + seg) * W2_STRIDE + o] = s;
        }
        __syncthreads();

        if (own && o_o < OUT_DIM) {
            float h2 = redp[(n_o * 4 + 0) * W2_STRIDE + o_o]
                     + redp[(n_o * 4 + 1) * W2_STRIDE + o_o]
                     + redp[(n_o * 4 + 2) * W2_STRIDE + o_o]
                     + redp[(n_o * 4 + 3) * W2_STRIDE + o_o] + b2v;
            v2 = v2 + (h2 - v2) / tau2v;
            float s = (v2 >= 1.f) ? 1.f : 0.f;
            v2 *= (1.f - s);
            accv += s;
        }
        __syncthreads();
    }

#pragma unroll
    for (int b = 0; b < BR; ++b)
        *(float4*)&g_state[((size_t)n * BR + b) * HH + h0] = st[b];
    *(float4*)&g_v1[(size_t)n * HH + h0] = v1;
    if (own && o_o < OUT_DIM) { g_v2[vidx] = v2; g_acc[vidx] = accv; }
}

// ---------------------------------------------------------------------------
// Final log_softmax
// ---------------------------------------------------------------------------
__global__ void final_kernel(float* __restrict__ out) {
    const int n = threadIdx.x;
    float f[OUT_DIM];
    float m = -1e30f;
#pragma unroll
    for (int o = 0; o < OUT_DIM; ++o) {
        f[o] = g_acc[n * OUT_DIM + o];
        m = fmaxf(m, f[o]);
    }
    float s = 0.f;
#pragma unroll
    for (int o = 0; o < OUT_DIM; ++o) s += expf(f[o] - m);
    float l = logf(s);
#pragma unroll
    for (int o = 0; o < OUT_DIM; ++o) out[n * OUT_DIM + o] = f[o] - m - l;
}

extern "C" void kernel_launch(void* const* d_in, const int* in_sizes, int n_in,
                              void* d_out, int out_size) {
    const float* x    = (const float*)d_in[0];
    const float* Wb   = (const float*)d_in[1];
    const float* bb   = (const float*)d_in[2];
    const float* taus = (const float*)d_in[3];
    const float* W2   = (const float*)d_in[4];
    const float* b2   = (const float*)d_in[5];
    const float* tau1 = (const float*)d_in[6];
    const float* tau2 = (const float*)d_in[7];
    float* out = (float*)d_out;

    static cudaStream_t s2 = nullptr;
    static cudaEvent_t evG[NCHUNK], evR[NCHUNK];
    if (!s2) {
        cudaStreamCreateWithFlags(&s2, cudaStreamNonBlocking);
        for (int i = 0; i < NCHUNK; ++i) {
            cudaEventCreateWithFlags(&evG[i], cudaEventDisableTiming);
            cudaEventCreateWithFlags(&evR[i], cudaEventDisableTiming);
        }
        cudaFuncSetAttribute(recur_kernel,
                             cudaFuncAttributeMaxDynamicSharedMemorySize,
                             SMEM_RECUR_BYTES);
    }

    init_kernel<<<4096, 256>>>(taus);

    dim3 ggrid(HH / 128, MC / 256, BR);   // (8, 25, 4) = 800 blocks
    for (int c = 0; c < NCHUNK; ++c) {
        const float* Xc = x + (size_t)c * MC * IN_DIM;
        const int yb = c & 1;
        // gemm(c) overwrites g_Y[yb]: must wait until recur(c-2) finished reading it
        if (c >= 2) cudaStreamWaitEvent(0, evR[c - 2], 0);
        gemm_kernel<<<ggrid, 256>>>(Xc, Wb, bb, yb);
        cudaEventRecord(evG[c], 0);
        // recur(c) on side stream: waits gemm(c); serialized with recur(c-1) by s2 order
        cudaStreamWaitEvent(s2, evG[c], 0);
        recur_kernel<<<128, 512, SMEM_RECUR_BYTES, s2>>>(W2, b2, tau1, tau2, yb);
        cudaEventRecord(evR[c], s2);
    }
    cudaStreamWaitEvent(0, evR[NCHUNK - 1], 0);
    final_kernel<<<1, 256>>>(out);
}

// round 14
// speedup vs baseline: 1.1480x; 1.0034x over previous
#include <cuda_runtime.h>
#include <cstdint>
#include <math.h>

#define T_STEPS 250
#define NN      256
#define IN_DIM  1024
#define HH      1024
#define OUT_DIM 35
#define BR      4
#define INB     256
#define TC      25
#define NCHUNK  (T_STEPS / TC)     // 10
#define MC      (TC * NN)          // 6400 rows per chunk

// Persistent state (device globals: no allocation allowed)
__device__ float g_state[NN * BR * HH];
__device__ float g_v1[NN * HH];
__device__ float g_alpha[BR * HH];
__device__ float g_v2[NN * OUT_DIM];
__device__ float g_acc[NN * OUT_DIM];
__device__ float g_Y[2][(size_t)MC * BR * HH];   // double-buffered chunk output

__global__ void init_kernel(const float* __restrict__ taus) {
    int idx = blockIdx.x * blockDim.x + threadIdx.x;
    g_state[idx] = 0.f;
    if (idx < NN * HH) g_v1[idx] = 0.f;
    if (idx < BR * HH) g_alpha[idx] = 1.f / (1.f + expf(-taus[idx]));
    if (idx < NN * OUT_DIM) { g_v2[idx] = 0.f; g_acc[idx] = 0.f; }
}

// ---------------------------------------------------------------------------
// Batched branch GEMM (unchanged best): tile 256(M) x 128(H), BK=16,
// 256 threads, 16x8 per thread, f32x2 packed on M-pairs.
// ---------------------------------------------------------------------------
__global__ __launch_bounds__(256, 1) void gemm_kernel(
    const float* __restrict__ Xc,
    const float* __restrict__ Wb,
    const float* __restrict__ bb,
    int ybuf)
{
    __shared__ float As[2][16][256];
    __shared__ float Bs[2][16][128];

    const int tid  = threadIdx.x;
    const int h0v  = blockIdx.x * 128;
    const int m0   = blockIdx.y * 256;
    const int br   = blockIdx.z;

    const int tx = tid & 15;
    const int ty = tid >> 4;
    const int mB = ty * 16;
    const int hB = tx * 8;

    const float* aptr = Xc + (size_t)(m0 + tid) * IN_DIM + br * INB;
    const int bk = tid >> 4, bh = (tid & 15) * 8;
    const float* bptr = Wb + ((size_t)br * INB + bk) * HH + h0v + bh;

    float* Yb = g_Y[ybuf];

    unsigned long long acc[8][8];
#pragma unroll
    for (int i = 0; i < 8; ++i)
#pragma unroll
        for (int j = 0; j < 8; ++j) acc[i][j] = 0ULL;

    {
        float4 a0 = *(const float4*)(aptr + 0);
        float4 a1 = *(const float4*)(aptr + 4);
        float4 a2 = *(const float4*)(aptr + 8);
        float4 a3 = *(const float4*)(aptr + 12);
        float4 b0 = *(const float4*)(bptr);
        float4 b1 = *(const float4*)(bptr + 4);
        As[0][ 0][tid] = a0.x; As[0][ 1][tid] = a0.y;
        As[0][ 2][tid] = a0.z; As[0][ 3][tid] = a0.w;
        As[0][ 4][tid] = a1.x; As[0][ 5][tid] = a1.y;
        As[0][ 6][tid] = a1.z; As[0][ 7][tid] = a1.w;
        As[0][ 8][tid] = a2.x; As[0][ 9][tid] = a2.y;
        As[0][10][tid] = a2.z; As[0][11][tid] = a2.w;
        As[0][12][tid] = a3.x; As[0][13][tid] = a3.y;
        As[0][14][tid] = a3.z; As[0][15][tid] = a3.w;
        *(float4*)&Bs[0][bk][bh]     = b0;
        *(float4*)&Bs[0][bk][bh + 4] = b1;
    }
    __syncthreads();

    int buf = 0;
#pragma unroll 1
    for (int k0 = 0; k0 < INB; k0 += 16) {
        const bool more = (k0 + 16) < INB;
        float4 na0, na1, na2, na3, nb0, nb1;
        if (more) {
            na0 = *(const float4*)(aptr + k0 + 16);
            na1 = *(const float4*)(aptr + k0 + 20);
            na2 = *(const float4*)(aptr + k0 + 24);
            na3 = *(const float4*)(aptr + k0 + 28);
            nb0 = *(const float4*)(bptr + (size_t)(k0 + 16) * HH);
            nb1 = *(const float4*)(bptr + (size_t)(k0 + 16) * HH + 4);
        }
#pragma unroll
        for (int k = 0; k < 16; ++k) {
            ulonglong2 aq0 = *(const ulonglong2*)&As[buf][k][mB];
            ulonglong2 aq1 = *(const ulonglong2*)&As[buf][k][mB + 4];
            ulonglong2 aq2 = *(const ulonglong2*)&As[buf][k][mB + 8];
            ulonglong2 aq3 = *(const ulonglong2*)&As[buf][k][mB + 12];
            unsigned long long a2p[8] = {aq0.x, aq0.y, aq1.x, aq1.y,
                                         aq2.x, aq2.y, aq3.x, aq3.y};
            float4 bf0 = *(const float4*)&Bs[buf][k][hB];
            float4 bf1 = *(const float4*)&Bs[buf][k][hB + 4];
            float bv[8] = {bf0.x, bf0.y, bf0.z, bf0.w,
                           bf1.x, bf1.y, bf1.z, bf1.w};
            unsigned long long bd[8];
#pragma unroll
            for (int j = 0; j < 8; ++j)
                asm("mov.b64 %0, {%1, %1};" : "=l"(bd[j]) : "f"(bv[j]));
#pragma unroll
            for (int i = 0; i < 8; ++i)
#pragma unroll
                for (int j = 0; j < 8; ++j)
                    asm("fma.rn.f32x2 %0, %1, %2, %0;"
                        : "+l"(acc[i][j]) : "l"(a2p[i]), "l"(bd[j]));
        }
        if (more) {
            const int nb = buf ^ 1;
            As[nb][ 0][tid] = na0.x; As[nb][ 1][tid] = na0.y;
            As[nb][ 2][tid] = na0.z; As[nb][ 3][tid] = na0.w;
            As[nb][ 4][tid] = na1.x; As[nb][ 5][tid] = na1.y;
            As[nb][ 6][tid] = na1.z; As[nb][ 7][tid] = na1.w;
            As[nb][ 8][tid] = na2.x; As[nb][ 9][tid] = na2.y;
            As[nb][10][tid] = na2.z; As[nb][11][tid] = na2.w;
            As[nb][12][tid] = na3.x; As[nb][13][tid] = na3.y;
            As[nb][14][tid] = na3.z; As[nb][15][tid] = na3.w;
            *(float4*)&Bs[nb][bk][bh]     = nb0;
            *(float4*)&Bs[nb][bk][bh + 4] = nb1;
            __syncthreads();
            buf = nb;
        }
    }

    float4 bias0 = *(const float4*)(bb + br * HH + h0v + hB);
    float4 bias1 = *(const float4*)(bb + br * HH + h0v + hB + 4);
    const float bvv[8] = {bias0.x, bias0.y, bias0.z, bias0.w,
                          bias1.x, bias1.y, bias1.z, bias1.w};
#pragma unroll
    for (int i = 0; i < 8; ++i) {
        float lo[8], hi[8];
#pragma unroll
        for (int j = 0; j < 8; ++j)
            asm("mov.b64 {%0, %1}, %2;" : "=f"(lo[j]), "=f"(hi[j]) : "l"(acc[i][j]));
        size_t r0 = (size_t)(m0 + mB + 2 * i);
        float* yp0 = &Yb[(r0 * BR + br) * HH + h0v + hB];
        float* yp1 = yp0 + (size_t)BR * HH;
        float4 w;
        w.x = lo[0] + bvv[0]; w.y = lo[1] + bvv[1];
        w.z = lo[2] + bvv[2]; w.w = lo[3] + bvv[3];
        *(float4*)yp0 = w;
        w.x = lo[4] + bvv[4]; w.y = lo[5] + bvv[5];
        w.z = lo[6] + bvv[6]; w.w = lo[7] + bvv[7];
        *(float4*)(yp0 + 4) = w;
        w.x = hi[0] + bvv[0]; w.y = hi[1] + bvv[1];
        w.z = hi[2] + bvv[2]; w.w = hi[3] + bvv[3];
        *(float4*)yp1 = w;
        w.x = hi[4] + bvv[4]; w.y = hi[5] + bvv[5];
        w.z = hi[6] + bvv[6]; w.w = hi[7] + bvv[7];
        *(float4*)(yp1 + 4) = w;
    }
}

// ---------------------------------------------------------------------------
// Fused recurrence with register double-buffered Y prefetch
// ---------------------------------------------------------------------------
#define W2_STRIDE 36
#define SM_W2   (HH * W2_STRIDE)
#define SM_RED  (2 * 256 * W2_STRIDE)
#define SM_REDP (2 * 4 * W2_STRIDE)
#define SMEM_RECUR_BYTES ((SM_W2 + SM_RED + SM_REDP) * 4)

__global__ __launch_bounds__(512, 1) void recur_kernel(
    const float* __restrict__ W2,
    const float* __restrict__ b2,
    const float* __restrict__ tau1p,
    const float* __restrict__ tau2p,
    int ybuf)
{
    extern __shared__ float sm[];
    float* W2s  = sm;
    float* red  = sm + SM_W2;
    float* redp = red + SM_RED;

    const int tid = threadIdx.x;
    const int n_l = tid >> 8;
    const int hq  = tid & 255;
    const int n   = blockIdx.x * 2 + n_l;
    const int h0  = hq * 4;
    const float* Yb = g_Y[ybuf];
    const float4* yb4 = (const float4*)(Yb + ((size_t)n * BR) * HH + h0);
    const size_t ystep = (size_t)NN * BR * HH / 4;   // float4 units per t
    const size_t bstep = HH / 4;                     // float4 units per branch

    for (int i = tid; i < SM_W2; i += 512) {
        int h = i / W2_STRIDE, o = i - h * W2_STRIDE;
        W2s[i] = (o < OUT_DIM) ? W2[h * OUT_DIM + o] : 0.f;
    }

    float4 st[BR], al[BR];
#pragma unroll
    for (int b = 0; b < BR; ++b) {
        st[b] = *(float4*)&g_state[((size_t)n * BR + b) * HH + h0];
        al[b] = *(const float4*)&g_alpha[b * HH + h0];
    }
    float4 v1 = *(float4*)&g_v1[(size_t)n * HH + h0];
    const float tau1v = *tau1p, tau2v = *tau2p;

    const bool own = (tid < 72);
    const int o_o = tid % 36, n_o = tid / 36;
    float v2 = 0.f, accv = 0.f, b2v = 0.f;
    int vidx = 0;
    if (own && o_o < OUT_DIM) {
        vidx = (blockIdx.x * 2 + n_o) * OUT_DIM + o_o;
        v2 = g_v2[vidx]; accv = g_acc[vidx]; b2v = b2[o_o];
    }

    // prefetch t=0 Y
    float4 ycur[BR], ynxt[BR];
#pragma unroll
    for (int b = 0; b < BR; ++b) ycur[b] = __ldg(yb4 + b * bstep);
    __syncthreads();

#pragma unroll 1
    for (int t = 0; t < TC; ++t) {
        // issue next t's loads early (latency hidden behind barriers below)
        if (t + 1 < TC) {
            const float4* yp = yb4 + (size_t)(t + 1) * ystep;
#pragma unroll
            for (int b = 0; b < BR; ++b) ynxt[b] = __ldg(yp + b * bstep);
        }

        float4 cb = {0.f, 0.f, 0.f, 0.f};
#pragma unroll
        for (int b = 0; b < BR; ++b) {
            st[b].x = al[b].x * st[b].x + (1.f - al[b].x) * ycur[b].x;
            st[b].y = al[b].y * st[b].y + (1.f - al[b].y) * ycur[b].y;
            st[b].z = al[b].z * st[b].z + (1.f - al[b].z) * ycur[b].z;
            st[b].w = al[b].w * st[b].w + (1.f - al[b].w) * ycur[b].w;
            cb.x += st[b].x; cb.y += st[b].y; cb.z += st[b].z; cb.w += st[b].w;
        }
        v1.x = v1.x + (cb.x - v1.x) / tau1v;
        v1.y = v1.y + (cb.y - v1.y) / tau1v;
        v1.z = v1.z + (cb.z - v1.z) / tau1v;
        v1.w = v1.w + (cb.w - v1.w) / tau1v;
        float s0 = (v1.x >= 1.f) ? 1.f : 0.f;
        float s1 = (v1.y >= 1.f) ? 1.f : 0.f;
        float s2 = (v1.z >= 1.f) ? 1.f : 0.f;
        float s3 = (v1.w >= 1.f) ? 1.f : 0.f;
        v1.x *= (1.f - s0); v1.y *= (1.f - s1);
        v1.z *= (1.f - s2); v1.w *= (1.f - s3);

        float4 a4[9];
#pragma unroll
        for (int q = 0; q < 9; ++q) a4[q] = make_float4(0.f, 0.f, 0.f, 0.f);
        if (s0 != 0.f) {
            const float4* w = (const float4*)&W2s[(h0 + 0) * W2_STRIDE];
#pragma unroll
            for (int q = 0; q < 9; ++q) { float4 v = w[q];
                a4[q].x += v.x; a4[q].y += v.y; a4[q].z += v.z; a4[q].w += v.w; }
        }
        if (s1 != 0.f) {
            const float4* w = (const float4*)&W2s[(h0 + 1) * W2_STRIDE];
#pragma unroll
            for (int q = 0; q < 9; ++q) { float4 v = w[q];
                a4[q].x += v.x; a4[q].y += v.y; a4[q].z += v.z; a4[q].w += v.w; }
        }
        if (s2 != 0.f) {
            const float4* w = (const float4*)&W2s[(h0 + 2) * W2_STRIDE];
#pragma unroll
            for (int q = 0; q < 9; ++q) { float4 v = w[q];
                a4[q].x += v.x; a4[q].y += v.y; a4[q].z += v.z; a4[q].w += v.w; }
        }
        if (s3 != 0.f) {
            const float4* w = (const float4*)&W2s[(h0 + 3) * W2_STRIDE];
#pragma unroll
            for (int q = 0; q < 9; ++q) { float4 v = w[q];
                a4[q].x += v.x; a4[q].y += v.y; a4[q].z += v.z; a4[q].w += v.w; }
        }
        float* rp = &red[((size_t)n_l * 256 + hq) * W2_STRIDE];
#pragma unroll
        for (int q = 0; q < 9; ++q) *(float4*)(rp + q * 4) = a4[q];
        __syncthreads();

        if (tid < 288) {
            int nl = tid / 144, r = tid % 144;
            int o = r % 36, seg = r / 36;
            const float* c = &red[((size_t)nl * 256 + seg * 64) * W2_STRIDE + o];
            float s = 0.f;
#pragma unroll 8
            for (int j = 0; j < 64; ++j) s += c[(size_t)j * W2_STRIDE];
            redp[(nl * 4 + seg) * W2_STRIDE + o] = s;
        }
        __syncthreads();

        if (own && o_o < OUT_DIM) {
            float h2 = redp[(n_o * 4 + 0) * W2_STRIDE + o_o]
                     + redp[(n_o * 4 + 1) * W2_STRIDE + o_o]
                     + redp[(n_o * 4 + 2) * W2_STRIDE + o_o]
                     + redp[(n_o * 4 + 3) * W2_STRIDE + o_o] + b2v;
            v2 = v2 + (h2 - v2) / tau2v;
            float s = (v2 >= 1.f) ? 1.f : 0.f;
            v2 *= (1.f - s);
            accv += s;
        }
        __syncthreads();

#pragma unroll
        for (int b = 0; b < BR; ++b) ycur[b] = ynxt[b];
    }

#pragma unroll
    for (int b = 0; b < BR; ++b)
        *(float4*)&g_state[((size_t)n * BR + b) * HH + h0] = st[b];
    *(float4*)&g_v1[(size_t)n * HH + h0] = v1;
    if (own && o_o < OUT_DIM) { g_v2[vidx] = v2; g_acc[vidx] = accv; }
}

// ---------------------------------------------------------------------------
// Final log_softmax
// ---------------------------------------------------------------------------
__global__ void final_kernel(float* __restrict__ out) {
    const int n = threadIdx.x;
    float f[OUT_DIM];
    float m = -1e30f;
#pragma unroll
    for (int o = 0; o < OUT_DIM; ++o) {
        f[o] = g_acc[n * OUT_DIM + o];
        m = fmaxf(m, f[o]);
    }
    float s = 0.f;
#pragma unroll
    for (int o = 0; o < OUT_DIM; ++o) s += expf(f[o] - m);
    float l = logf(s);
#pragma unroll
    for (int o = 0; o < OUT_DIM; ++o) out[n * OUT_DIM + o] = f[o] - m - l;
}

extern "C" void kernel_launch(void* const* d_in, const int* in_sizes, int n_in,
                              void* d_out, int out_size) {
    const float* x    = (const float*)d_in[0];
    const float* Wb   = (const float*)d_in[1];
    const float* bb   = (const float*)d_in[2];
    const float* taus = (const float*)d_in[3];
    const float* W2   = (const float*)d_in[4];
    const float* b2   = (const float*)d_in[5];
    const float* tau1 = (const float*)d_in[6];
    const float* tau2 = (const float*)d_in[7];
    float* out = (float*)d_out;

    static cudaStream_t s2 = nullptr;
    static cudaEvent_t evG[NCHUNK], evR[NCHUNK];
    if (!s2) {
        cudaStreamCreateWithFlags(&s2, cudaStreamNonBlocking);
        for (int i = 0; i < NCHUNK; ++i) {
            cudaEventCreateWithFlags(&evG[i], cudaEventDisableTiming);
            cudaEventCreateWithFlags(&evR[i], cudaEventDisableTiming);
        }
        cudaFuncSetAttribute(recur_kernel,
                             cudaFuncAttributeMaxDynamicSharedMemorySize,
                             SMEM_RECUR_BYTES);
    }

    init_kernel<<<4096, 256>>>(taus);

    dim3 ggrid(HH / 128, MC / 256, BR);   // (8, 25, 4) = 800 blocks
    for (int c = 0; c < NCHUNK; ++c) {
        const float* Xc = x + (size_t)c * MC * IN_DIM;
        const int yb = c & 1;
        if (c >= 2) cudaStreamWaitEvent(0, evR[c - 2], 0);
        gemm_kernel<<<ggrid, 256>>>(Xc, Wb, bb, yb);
        cudaEventRecord(evG[c], 0);
        cudaStreamWaitEvent(s2, evG[c], 0);
        recur_kernel<<<128, 512, SMEM_RECUR_BYTES, s2>>>(W2, b2, tau1, tau2, yb);
        cudaEventRecord(evR[c], s2);
    }
    cudaStreamWaitEvent(0, evR[NCHUNK - 1], 0);
    final_kernel<<<1, 256>>>(out);
}